// round 5
// baseline (speedup 1.0000x reference)
#include <cuda_runtime.h>
#include <math.h>
#include <string.h>

#define LEN   2048
#define BATCH 64
#define NH    8
#define SCH   64          // scores chunk
#define NSC   32          // # score chunks
#define RCH   128         // read chunk
#define NRC   16          // # read chunks

#define FFMA2(acc, x, y) \
    asm("fma.rn.f32x2 %0, %1, %2, %0;" : "+l"(acc) : "l"(x), "l"(y))

__device__ __forceinline__ float f32x2_sum(unsigned long long v) {
    float2 f;
    memcpy(&f, &v, 8);
    return f.x + f.y;
}

// ---------------- scratch (device globals; no allocation) ----------------
__device__ float g_q[BATCH * 2048];              // q[b][h*256+k]
__device__ float g_wexp[NSC * BATCH * SCH * NH]; // exp weights [cc][b][h*64+l]
__device__ float g_mc[NSC * BATCH * NH];         // chunk-local max
__device__ float g_sc[NSC * BATCH * NH];         // chunk-local sum-exp
__device__ float g_rpart[NRC * BATCH * 2048];    // normalized read partials
__device__ float g_opart[16 * BATCH * 256];      // kc partials of out

// ---------------- K1: q GEMM (single kernel): q = query@Wq + bq -----------
// grid 256 (jt of 8 cols), 256 thr: tid = jg*64 + b, 2 cols per thread
__global__ void __launch_bounds__(256) k_qgemm(const float* __restrict__ query,
                                               const float* __restrict__ Wq,
                                               const float* __restrict__ bq) {
    __shared__ float w_s[32][10];    // [k][j] pad
    __shared__ float q_s[64][33];    // [b][k] pad
    int jt = blockIdx.x;
    int tid = threadIdx.x;
    int b = tid & 63, jg = tid >> 6;       // jg 0..3, 2 j each
    float acc0 = 0.f, acc1 = 0.f;
    for (int kt = 0; kt < 8; kt++) {
        {   // Wq tile 32k x 8j : 256 elems, 1 per thread
            int k = tid >> 3, j = tid & 7;
            w_s[k][j] = Wq[(size_t)(kt * 32 + k) * 2048 + jt * 8 + j];
        }
        for (int e = tid; e < 2048; e += 256) {   // query tile 64b x 32k
            int bb = e >> 5, kk = e & 31;
            q_s[bb][kk] = query[bb * 256 + kt * 32 + kk];
        }
        __syncthreads();
#pragma unroll
        for (int kk = 0; kk < 32; kk++) {
            float qv = q_s[b][kk];
            acc0 += qv * w_s[kk][jg * 2 + 0];
            acc1 += qv * w_s[kk][jg * 2 + 1];
        }
        __syncthreads();
    }
    int j0 = jt * 8 + jg * 2;
    g_q[b * 2048 + j0 + 0] = acc0 + bq[j0 + 0];
    g_q[b * 2048 + j0 + 1] = acc1 + bq[j0 + 1];
}

// ---------------- K2: scores + chunk-local softmax stats ------------------
// grid (16 cc, 64 b) x2 launches, 256 thr, <=64 regs (4 CTA/SM)
__global__ void __launch_bounds__(256, 4) k_scores(const float* __restrict__ keys,
                                                   const float* __restrict__ rpe,
                                                   const int* __restrict__ steps,
                                                   int coff) {
    int c = blockIdx.x + coff, b = blockIdx.y;
    int lbase = c * SCH;
    int n = steps[b];
    if (lbase >= n) return;
    int nv = n - lbase; if (nv > SCH) nv = SCH;
    int tid = threadIdx.x;

    __shared__ __align__(16) float q_s[2048];
    __shared__ float r_s[SCH];
    __shared__ float s_s[8 * 68];

    for (int i = tid; i < 2048; i += 256) q_s[i] = g_q[b * 2048 + i];
    if (tid < SCH) r_s[tid] = rpe[(lbase + tid) * 64 + b];
    __syncthreads();

    // ---- phase A: 1 row per warp pass, packed f32x2 FMA ----
    {
        int w = tid >> 5, lane = tid & 31;
        int hg = lane >> 3, kl = lane & 7;
        int h0 = hg * 2;
        const ulonglong2* qa0 = ((const ulonglong2*)(q_s + h0 * 256)) + kl;
        const ulonglong2* qa1 = ((const ulonglong2*)(q_s + (h0 + 1) * 256)) + kl;
        for (int l = w; l < nv; l += 8) {
            const ulonglong2* kp =
                ((const ulonglong2*)(keys + ((size_t)(lbase + l) * 64 + b) * 256)) + kl;
            unsigned long long a0 = 0ull, a1 = 0ull;
#pragma unroll
            for (int jj = 0; jj < 8; jj++) {
                ulonglong2 kv = kp[8 * jj];
                ulonglong2 q0 = qa0[8 * jj];
                ulonglong2 q1 = qa1[8 * jj];
                FFMA2(a0, kv.x, q0.x);
                FFMA2(a0, kv.y, q0.y);
                FFMA2(a1, kv.x, q1.x);
                FFMA2(a1, kv.y, q1.y);
            }
            float s0 = f32x2_sum(a0);
            float s1 = f32x2_sum(a1);
#pragma unroll
            for (int o = 1; o < 8; o <<= 1) {
                s0 += __shfl_xor_sync(0xffffffffu, s0, o);
                s1 += __shfl_xor_sync(0xffffffffu, s1, o);
            }
            float r = r_s[l];
            if (kl == 0) s_s[h0 * 68 + l]       = s0 * r;
            if (kl == 1) s_s[(h0 + 1) * 68 + l] = s1 * r;
        }
    }
    __syncthreads();

    // ---- phase B: chunk-local max + sum-exp; write exp weights [h][l] ----
    {
        int h = tid >> 5, lane = tid & 31;
        float m = -3.0e38f;
        for (int l = lane; l < nv; l += 32) m = fmaxf(m, s_s[h * 68 + l]);
#pragma unroll
        for (int o = 16; o > 0; o >>= 1) m = fmaxf(m, __shfl_xor_sync(0xffffffffu, m, o));
        float s = 0.f;
        size_t wbase = (size_t)(c * 64 + b) * 512 + h * 64;
        for (int l = lane; l < nv; l += 32) {
            float p = __expf(s_s[h * 68 + l] - m);
            g_wexp[wbase + l] = p;
            s += p;
        }
#pragma unroll
        for (int o = 16; o > 0; o >>= 1) s += __shfl_xor_sync(0xffffffffu, s, o);
        if (lane == 0) {
            g_mc[(c * 64 + b) * 8 + h] = m;
            g_sc[(c * 64 + b) * 8 + h] = s;
        }
    }
}

// ---------------- K3: weighted read, normalized on the fly ----------------
// grid (16 cb of 128, 64 b), 256 thr (thread = v)
__global__ void __launch_bounds__(256, 4) k_read(const float* __restrict__ vals,
                                                 const int* __restrict__ steps) {
    int cb = blockIdx.x, b = blockIdx.y;
    int lbase = cb * RCH;
    int n = steps[b];
    if (lbase >= n) return;
    int nv = n - lbase; if (nv > RCH) nv = RCH;
    int tid = threadIdx.x;
    int nc_all = (n + SCH - 1) >> 6;

    __shared__ float f_s[8][32];     // merge factor [h][cc]
    __shared__ __align__(16) float w_s[RCH * 8];   // normalized weights [l][h]

    // ---- factors: warp h handles head h, lane = cc ----
    {
        int h = tid >> 5, cc = tid & 31;
        int valid = cc < nc_all;
        float m = valid ? g_mc[(cc * 64 + b) * 8 + h] : -3.0e38f;
        float s = valid ? g_sc[(cc * 64 + b) * 8 + h] : 0.f;
        float M = m;
#pragma unroll
        for (int o = 16; o > 0; o >>= 1) M = fmaxf(M, __shfl_xor_sync(0xffffffffu, M, o));
        float e = __expf(m - M);
        float denom = e * s;
#pragma unroll
        for (int o = 16; o > 0; o >>= 1) denom += __shfl_xor_sync(0xffffffffu, denom, o);
        f_s[h][cc] = e / denom;
    }
    __syncthreads();

    // ---- stage normalized weights (coalesced gmem reads) ----
    {
        int cc0 = cb * 2;
#pragma unroll
        for (int it = 0; it < 4; it++) {
            int i = tid + it * 256;          // i = h*128 + l
            int h = i >> 7, l = i & 127;
            int cc = cc0 + (l >> 6);
            float wv = g_wexp[(size_t)(cc * 64 + b) * 512 + h * 64 + (l & 63)];
            w_s[l * 8 + h] = wv * f_s[h][cc];
        }
    }
    __syncthreads();

    // ---- stream vals: acc[h] += w[l][h] * vals[l][b][tid] ----
    float acc[8];
#pragma unroll
    for (int h = 0; h < 8; h++) acc[h] = 0.f;
    const float* vp = vals + ((size_t)lbase * 64 + b) * 256 + tid;
    const float4* w4 = (const float4*)w_s;
    int l = 0;
    for (; l + 16 <= nv; l += 16) {
        float v[16];
#pragma unroll
        for (int i = 0; i < 16; i++) v[i] = vp[(size_t)(l + i) * 16384];
#pragma unroll
        for (int i = 0; i < 16; i++) {
            float4 w0 = w4[(l + i) * 2], w1 = w4[(l + i) * 2 + 1];
            acc[0] += w0.x * v[i]; acc[1] += w0.y * v[i];
            acc[2] += w0.z * v[i]; acc[3] += w0.w * v[i];
            acc[4] += w1.x * v[i]; acc[5] += w1.y * v[i];
            acc[6] += w1.z * v[i]; acc[7] += w1.w * v[i];
        }
    }
    for (; l < nv; l++) {
        float v = vp[(size_t)l * 16384];
        float4 w0 = w4[l * 2], w1 = w4[l * 2 + 1];
        acc[0] += w0.x * v; acc[1] += w0.y * v; acc[2] += w0.z * v; acc[3] += w0.w * v;
        acc[4] += w1.x * v; acc[5] += w1.y * v; acc[6] += w1.z * v; acc[7] += w1.w * v;
    }
    size_t pbase = ((size_t)cb * 64 + b) * 2048;
#pragma unroll
    for (int h = 0; h < 8; h++) g_rpart[pbase + h * 256 + tid] = acc[h];
}

// ---------------- K4: out partial GEMM with predicated chunk reduce -------
__global__ void __launch_bounds__(256) k_outgemm(const float* __restrict__ Wa,
                                                 const int* __restrict__ steps) {
    int kc = blockIdx.x, bt = blockIdx.y;
    int tid = threadIdx.x;
    __shared__ __align__(16) float R_s[128 * 8];   // [k][bi]
    __shared__ int nc_s[8];
    if (tid < 8) nc_s[tid] = (steps[bt * 8 + tid] + RCH - 1) >> 7;
    __syncthreads();

    for (int i = tid; i < 1024; i += 256) {
        int bi = i >> 7, k = i & 127;
        int b = bt * 8 + bi;
        int nc = nc_s[bi];
        float s = 0.f;
#pragma unroll
        for (int cc = 0; cc < 16; cc++)
            if (cc < nc) s += g_rpart[((size_t)cc * 64 + b) * 2048 + kc * 128 + k];
        R_s[k * 8 + bi] = s;
    }
    __syncthreads();

    float acc[8];
#pragma unroll
    for (int i = 0; i < 8; i++) acc[i] = 0.f;
    const float4* R4 = (const float4*)R_s;
#pragma unroll 4
    for (int k = 0; k < 128; k++) {
        float wa = Wa[(size_t)(kc * 128 + k) * 256 + tid];
        float4 r0 = R4[k * 2], r1 = R4[k * 2 + 1];
        acc[0] += r0.x * wa; acc[1] += r0.y * wa; acc[2] += r0.z * wa; acc[3] += r0.w * wa;
        acc[4] += r1.x * wa; acc[5] += r1.y * wa; acc[6] += r1.z * wa; acc[7] += r1.w * wa;
    }
#pragma unroll
    for (int bi = 0; bi < 8; bi++)
        g_opart[((size_t)kc * 64 + bt * 8 + bi) * 256 + tid] = acc[bi];
}

// ---------------- K5: final reduce + bias ---------------------------------
__global__ void __launch_bounds__(256) k_final(const float* __restrict__ ba,
                                               float* __restrict__ out) {
    int b = blockIdx.x, vo = threadIdx.x;
    float s = ba[vo];
#pragma unroll
    for (int cc = 0; cc < 16; cc++) s += g_opart[((size_t)cc * 64 + b) * 256 + vo];
    out[b * 256 + vo] = s;
}

// ---------------- launch --------------------------------------------------
extern "C" void kernel_launch(void* const* d_in, const int* in_sizes, int n_in,
                              void* d_out, int out_size) {
    const float* query = (const float*)d_in[0];
    const float* keys  = (const float*)d_in[1];
    const float* vals  = (const float*)d_in[2];
    const float* rpe   = (const float*)d_in[3];
    const float* Wq    = (const float*)d_in[4];
    const float* bq    = (const float*)d_in[5];
    const float* Wa    = (const float*)d_in[6];
    const float* ba    = (const float*)d_in[7];
    const int*   steps = (const int*)d_in[8];
    float* out = (float*)d_out;

    k_qgemm<<<256, 256>>>(query, Wq, bq);
    k_scores<<<dim3(16, BATCH), 256>>>(keys, rpe, steps, 0);
    k_scores<<<dim3(16, BATCH), 256>>>(keys, rpe, steps, 16);
    k_read<<<dim3(NRC, BATCH), 256>>>(vals, steps);       // 4th launch -> profiled
    k_outgemm<<<dim3(16, 8), 256>>>(Wa, steps);
    k_final<<<64, 256>>>(ba, out);
}

// round 6
// speedup vs baseline: 1.2370x; 1.2370x over previous
#include <cuda_runtime.h>
#include <math.h>
#include <string.h>

#define LEN   2048
#define BATCH 64
#define NH    8
#define SCH   64          // scores chunk
#define NSC   32          // # score chunks
#define RCH   128         // read chunk
#define NRC   16          // # read chunks

#define FFMA2(acc, x, y) \
    asm("fma.rn.f32x2 %0, %1, %2, %0;" : "+l"(acc) : "l"(x), "l"(y))
#define PACK2(out, lo, hi) \
    asm("mov.b64 %0, {%1, %2};" : "=l"(out) : "f"(lo), "f"(hi))
#define UNPACK2(lo, hi, in) \
    asm("mov.b64 {%0, %1}, %2;" : "=f"(lo), "=f"(hi) : "l"(in))

__device__ __forceinline__ float f32x2_sum(unsigned long long v) {
    float2 f;
    memcpy(&f, &v, 8);
    return f.x + f.y;
}

// ---------------- scratch (device globals; no allocation) ----------------
__device__ float g_q[BATCH * 2048];              // q[b][h*256+k]
__device__ float g_wexp[NSC * BATCH * SCH * NH]; // exp weights [cc][b][h*64+l]
__device__ float g_mc[NSC * BATCH * NH];         // chunk-local max
__device__ float g_sc[NSC * BATCH * NH];         // chunk-local sum-exp
__device__ float g_rpart[NRC * BATCH * 2048];    // normalized read partials
__device__ float g_opart[16 * BATCH * 256];      // kc partials of out

// ---------------- K1: q GEMM: q = query@Wq + bq (3-way j split) -----------
// per launch: grid = #jt, 256 thr: tid = jg*64 + b, 2 cols per thread
__global__ void __launch_bounds__(256) k_qgemm(const float* __restrict__ query,
                                               const float* __restrict__ Wq,
                                               const float* __restrict__ bq,
                                               int jt_off) {
    __shared__ float w_s[32][10];    // [k][j] pad
    __shared__ float q_s[64][33];    // [b][k] pad (conflict-free compute)
    int jt = blockIdx.x + jt_off;
    int tid = threadIdx.x;
    int b = tid & 63, jg = tid >> 6;       // jg 0..3, 2 j each
    float acc0 = 0.f, acc1 = 0.f;
    for (int kt = 0; kt < 8; kt++) {
        {   // Wq tile 32k x 8j
            int k = tid >> 3, j = tid & 7;
            w_s[k][j] = Wq[(size_t)(kt * 32 + k) * 2048 + jt * 8 + j];
        }
#pragma unroll
        for (int it = 0; it < 2; it++) {   // query tile 64b x 32k, float4
            int f4 = tid + it * 256;       // 512 float4s
            int bb = f4 >> 3, k4 = f4 & 7;
            float4 v = ((const float4*)query)[bb * 64 + kt * 8 + k4];
            q_s[bb][k4 * 4 + 0] = v.x;
            q_s[bb][k4 * 4 + 1] = v.y;
            q_s[bb][k4 * 4 + 2] = v.z;
            q_s[bb][k4 * 4 + 3] = v.w;
        }
        __syncthreads();
#pragma unroll
        for (int kk = 0; kk < 32; kk++) {
            float qv = q_s[b][kk];
            acc0 += qv * w_s[kk][jg * 2 + 0];
            acc1 += qv * w_s[kk][jg * 2 + 1];
        }
        __syncthreads();
    }
    int j0 = jt * 8 + jg * 2;
    g_q[b * 2048 + j0 + 0] = acc0 + bq[j0 + 0];
    g_q[b * 2048 + j0 + 1] = acc1 + bq[j0 + 1];
}

// ---------------- K2: scores + chunk-local softmax stats ------------------
// grid (32 cc, 64 b), 256 thr. 2-row pipelined, f32x2, natural regs.
__global__ void __launch_bounds__(256) k_scores(const float* __restrict__ keys,
                                                const float* __restrict__ rpe,
                                                const int* __restrict__ steps) {
    int c = blockIdx.x, b = blockIdx.y;
    int lbase = c * SCH;
    int n = steps[b];
    if (lbase >= n) return;
    int nv = n - lbase; if (nv > SCH) nv = SCH;
    int tid = threadIdx.x;

    __shared__ __align__(16) float q_s[2048];
    __shared__ float r_s[SCH];
    __shared__ float s_s[8 * 68];

    for (int it = 0; it < 2; it++) {       // q via float4
        int f4 = tid + it * 256;
        ((float4*)q_s)[f4] = ((const float4*)g_q)[b * 512 + f4];
    }
    if (tid < SCH) r_s[tid] = rpe[(lbase + tid) * 64 + b];
    __syncthreads();

    // ---- phase A: 2 rows per warp pass, f32x2, half-split k loop ----
    {
        int w = tid >> 5, lane = tid & 31;
        int hg = lane >> 3, kl = lane & 7;
        int h0 = hg * 2;
        const ulonglong2* qa0 = ((const ulonglong2*)(q_s + h0 * 256)) + kl;
        const ulonglong2* qa1 = ((const ulonglong2*)(q_s + (h0 + 1) * 256)) + kl;
        for (int l0 = w; l0 < nv; l0 += 16) {
            int l1 = l0 + 8;
            int has1 = (l1 < nv);
            const ulonglong2* kp0 =
                ((const ulonglong2*)(keys + ((size_t)(lbase + l0) * 64 + b) * 256)) + kl;
            const ulonglong2* kp1 =
                ((const ulonglong2*)(keys + ((size_t)(lbase + (has1 ? l1 : l0)) * 64 + b) * 256)) + kl;
            unsigned long long a0 = 0ull, a1 = 0ull, c0 = 0ull, c1 = 0ull;
#pragma unroll 1
            for (int half = 0; half < 2; half++) {
#pragma unroll
                for (int jj = 0; jj < 4; jj++) {
                    int idx = (half * 4 + jj) * 8;
                    ulonglong2 k0 = kp0[idx];
                    ulonglong2 k1 = kp1[idx];
                    ulonglong2 q0 = qa0[idx];
                    ulonglong2 q1 = qa1[idx];
                    FFMA2(a0, k0.x, q0.x);
                    FFMA2(a0, k0.y, q0.y);
                    FFMA2(a1, k0.x, q1.x);
                    FFMA2(a1, k0.y, q1.y);
                    FFMA2(c0, k1.x, q0.x);
                    FFMA2(c0, k1.y, q0.y);
                    FFMA2(c1, k1.x, q1.x);
                    FFMA2(c1, k1.y, q1.y);
                }
            }
            float s0 = f32x2_sum(a0);
            float s1 = f32x2_sum(a1);
            float t0 = f32x2_sum(c0);
            float t1 = f32x2_sum(c1);
#pragma unroll
            for (int o = 1; o < 8; o <<= 1) {
                s0 += __shfl_xor_sync(0xffffffffu, s0, o);
                s1 += __shfl_xor_sync(0xffffffffu, s1, o);
                t0 += __shfl_xor_sync(0xffffffffu, t0, o);
                t1 += __shfl_xor_sync(0xffffffffu, t1, o);
            }
            float r0 = r_s[l0];
            if (kl == 0) s_s[h0 * 68 + l0]       = s0 * r0;
            if (kl == 1) s_s[(h0 + 1) * 68 + l0] = s1 * r0;
            if (has1) {
                float r1 = r_s[l1];
                if (kl == 0) s_s[h0 * 68 + l1]       = t0 * r1;
                if (kl == 1) s_s[(h0 + 1) * 68 + l1] = t1 * r1;
            }
        }
    }
    __syncthreads();

    // ---- phase B: chunk-local max + sum-exp; write exp weights [h][l] ----
    {
        int h = tid >> 5, lane = tid & 31;
        float m = -3.0e38f;
        for (int l = lane; l < nv; l += 32) m = fmaxf(m, s_s[h * 68 + l]);
#pragma unroll
        for (int o = 16; o > 0; o >>= 1) m = fmaxf(m, __shfl_xor_sync(0xffffffffu, m, o));
        float s = 0.f;
        size_t wbase = (size_t)(c * 64 + b) * 512 + h * 64;
        for (int l = lane; l < nv; l += 32) {
            float p = __expf(s_s[h * 68 + l] - m);
            g_wexp[wbase + l] = p;
            s += p;
        }
#pragma unroll
        for (int o = 16; o > 0; o >>= 1) s += __shfl_xor_sync(0xffffffffu, s, o);
        if (lane == 0) {
            g_mc[(c * 64 + b) * 8 + h] = m;
            g_sc[(c * 64 + b) * 8 + h] = s;
        }
    }
}

// ---------------- K3: weighted read (f32x2), normalized on the fly --------
// grid (16 cb of 128, 64 b), 256 thr (thread = v)
__global__ void __launch_bounds__(256) k_read(const float* __restrict__ vals,
                                              const int* __restrict__ steps) {
    int cb = blockIdx.x, b = blockIdx.y;
    int lbase = cb * RCH;
    int n = steps[b];
    if (lbase >= n) return;
    int nv = n - lbase; if (nv > RCH) nv = RCH;
    int tid = threadIdx.x;
    int nc_all = (n + SCH - 1) >> 6;

    __shared__ float f_s[8][32];     // merge factor [h][cc]
    __shared__ __align__(16) float w_s[RCH * 8];   // normalized weights [l][h]

    // ---- factors: warp h handles head h, lane = cc ----
    {
        int h = tid >> 5, cc = tid & 31;
        int valid = cc < nc_all;
        float m = valid ? g_mc[(cc * 64 + b) * 8 + h] : -3.0e38f;
        float s = valid ? g_sc[(cc * 64 + b) * 8 + h] : 0.f;
        float M = m;
#pragma unroll
        for (int o = 16; o > 0; o >>= 1) M = fmaxf(M, __shfl_xor_sync(0xffffffffu, M, o));
        float e = __expf(m - M);
        float denom = e * s;
#pragma unroll
        for (int o = 16; o > 0; o >>= 1) denom += __shfl_xor_sync(0xffffffffu, denom, o);
        f_s[h][cc] = e / denom;
    }
    __syncthreads();

    // ---- stage normalized weights (coalesced gmem reads) ----
    {
        int cc0 = cb * 2;
#pragma unroll
        for (int it = 0; it < 4; it++) {
            int i = tid + it * 256;          // i = h*128 + l
            int h = i >> 7, l = i & 127;
            int cc = cc0 + (l >> 6);
            float wv = g_wexp[(size_t)(cc * 64 + b) * 512 + h * 64 + (l & 63)];
            w_s[l * 8 + h] = wv * f_s[h][cc];
        }
    }
    __syncthreads();

    // ---- stream vals: packed h-pair accumulators ----
    unsigned long long ah[4];
#pragma unroll
    for (int i = 0; i < 4; i++) ah[i] = 0ull;
    const float* vp = vals + ((size_t)lbase * 64 + b) * 256 + tid;
    const unsigned long long* wll = (const unsigned long long*)w_s;
    int l = 0;
    for (; l + 16 <= nv; l += 16) {
        float v[16];
#pragma unroll
        for (int i = 0; i < 16; i++) v[i] = vp[(size_t)(l + i) * 16384];
#pragma unroll
        for (int i = 0; i < 16; i++) {
            unsigned long long vv;
            PACK2(vv, v[i], v[i]);
#pragma unroll
            for (int hp = 0; hp < 4; hp++)
                FFMA2(ah[hp], wll[(l + i) * 4 + hp], vv);
        }
    }
    for (; l < nv; l++) {
        float v = vp[(size_t)l * 16384];
        unsigned long long vv;
        PACK2(vv, v, v);
#pragma unroll
        for (int hp = 0; hp < 4; hp++)
            FFMA2(ah[hp], wll[l * 4 + hp], vv);
    }
    size_t pbase = ((size_t)cb * 64 + b) * 2048;
#pragma unroll
    for (int hp = 0; hp < 4; hp++) {
        float lo, hi;
        UNPACK2(lo, hi, ah[hp]);
        g_rpart[pbase + (hp * 2 + 0) * 256 + tid] = lo;
        g_rpart[pbase + (hp * 2 + 1) * 256 + tid] = hi;
    }
}

// ---------------- K4: out partial GEMM with predicated chunk reduce -------
__global__ void __launch_bounds__(256) k_outgemm(const float* __restrict__ Wa,
                                                 const int* __restrict__ steps) {
    int kc = blockIdx.x, bt = blockIdx.y;
    int tid = threadIdx.x;
    __shared__ __align__(16) float R_s[128 * 8];   // [k][bi]
    __shared__ int nc_s[8];
    if (tid < 8) nc_s[tid] = (steps[bt * 8 + tid] + RCH - 1) >> 7;
    __syncthreads();

    for (int i = tid; i < 1024; i += 256) {
        int bi = i >> 7, k = i & 127;
        int b = bt * 8 + bi;
        int nc = nc_s[bi];
        float s = 0.f;
#pragma unroll
        for (int cc = 0; cc < 16; cc++)
            if (cc < nc) s += g_rpart[((size_t)cc * 64 + b) * 2048 + kc * 128 + k];
        R_s[k * 8 + bi] = s;
    }
    __syncthreads();

    float acc[8];
#pragma unroll
    for (int i = 0; i < 8; i++) acc[i] = 0.f;
    const float4* R4 = (const float4*)R_s;
#pragma unroll 4
    for (int k = 0; k < 128; k++) {
        float wa = Wa[(size_t)(kc * 128 + k) * 256 + tid];
        float4 r0 = R4[k * 2], r1 = R4[k * 2 + 1];
        acc[0] += r0.x * wa; acc[1] += r0.y * wa; acc[2] += r0.z * wa; acc[3] += r0.w * wa;
        acc[4] += r1.x * wa; acc[5] += r1.y * wa; acc[6] += r1.z * wa; acc[7] += r1.w * wa;
    }
#pragma unroll
    for (int bi = 0; bi < 8; bi++)
        g_opart[((size_t)kc * 64 + bt * 8 + bi) * 256 + tid] = acc[bi];
}

// ---------------- K5: final reduce + bias ---------------------------------
__global__ void __launch_bounds__(256) k_final(const float* __restrict__ ba,
                                               float* __restrict__ out) {
    int b = blockIdx.x, vo = threadIdx.x;
    float s = ba[vo];
#pragma unroll
    for (int cc = 0; cc < 16; cc++) s += g_opart[((size_t)cc * 64 + b) * 256 + vo];
    out[b * 256 + vo] = s;
}

// ---------------- launch --------------------------------------------------
extern "C" void kernel_launch(void* const* d_in, const int* in_sizes, int n_in,
                              void* d_out, int out_size) {
    const float* query = (const float*)d_in[0];
    const float* keys  = (const float*)d_in[1];
    const float* vals  = (const float*)d_in[2];
    const float* rpe   = (const float*)d_in[3];
    const float* Wq    = (const float*)d_in[4];
    const float* bq    = (const float*)d_in[5];
    const float* Wa    = (const float*)d_in[6];
    const float* ba    = (const float*)d_in[7];
    const int*   steps = (const int*)d_in[8];
    float* out = (float*)d_out;

    k_qgemm<<<86, 256>>>(query, Wq, bq, 0);
    k_qgemm<<<85, 256>>>(query, Wq, bq, 86);
    k_qgemm<<<85, 256>>>(query, Wq, bq, 171);
    k_scores<<<dim3(NSC, BATCH), 256>>>(keys, rpe, steps);   // 4th -> profiled
    k_read<<<dim3(NRC, BATCH), 256>>>(vals, steps);
    k_outgemm<<<dim3(16, 8), 256>>>(Wa, steps);
    k_final<<<64, 256>>>(ba, out);
}

// round 7
// speedup vs baseline: 1.6126x; 1.3037x over previous
#include <cuda_runtime.h>
#include <math.h>
#include <string.h>

#define LEN   2048
#define BATCH 64
#define NH    8
#define SCH   64          // scores chunk
#define NSC   32          // # score chunks
#define RCH   128         // read chunk
#define NRC   16          // # read chunks

#define FFMA2(acc, x, y) \
    asm("fma.rn.f32x2 %0, %1, %2, %0;" : "+l"(acc) : "l"(x), "l"(y))
#define PACK2(out, lo, hi) \
    asm("mov.b64 %0, {%1, %2};" : "=l"(out) : "f"(lo), "f"(hi))
#define UNPACK2(lo, hi, in) \
    asm("mov.b64 {%0, %1}, %2;" : "=f"(lo), "=f"(hi) : "l"(in))

// ---------------- scratch (device globals; no allocation) ----------------
__device__ float g_q[BATCH * 2048];              // q[b][h*256+k]
__device__ float g_wexp[NSC * BATCH * SCH * NH]; // exp weights [cc][b][h*64+l]
__device__ float g_mc[NSC * BATCH * NH];         // chunk-local max
__device__ float g_sc[NSC * BATCH * NH];         // chunk-local sum-exp
__device__ float g_rpart[NRC * BATCH * 2048];    // normalized read partials
__device__ float g_opart[16 * BATCH * 256];      // kc partials of out

// ---------------- K1: q GEMM: q = query@Wq + bq ---------------------------
// grid 256 (jt of 8 cols), 256 thr: tid = jg*64 + b, 2 cols per thread
__global__ void __launch_bounds__(256) k_qgemm(const float* __restrict__ query,
                                               const float* __restrict__ Wq,
                                               const float* __restrict__ bq) {
    __shared__ float w_s[32][10];    // [k][j] pad
    __shared__ float q_s[64][33];    // [b][k] pad
    int jt = blockIdx.x;
    int tid = threadIdx.x;
    int b = tid & 63, jg = tid >> 6;
    float acc0 = 0.f, acc1 = 0.f;
    for (int kt = 0; kt < 8; kt++) {
        {   // Wq tile 32k x 8j
            int k = tid >> 3, j = tid & 7;
            w_s[k][j] = Wq[(size_t)(kt * 32 + k) * 2048 + jt * 8 + j];
        }
#pragma unroll
        for (int it = 0; it < 2; it++) {   // query tile 64b x 32k, float4
            int f4 = tid + it * 256;
            int bb = f4 >> 3, k4 = f4 & 7;
            float4 v = ((const float4*)query)[bb * 64 + kt * 8 + k4];
            q_s[bb][k4 * 4 + 0] = v.x;
            q_s[bb][k4 * 4 + 1] = v.y;
            q_s[bb][k4 * 4 + 2] = v.z;
            q_s[bb][k4 * 4 + 3] = v.w;
        }
        __syncthreads();
#pragma unroll
        for (int kk = 0; kk < 32; kk++) {
            float qv = q_s[b][kk];
            acc0 += qv * w_s[kk][jg * 2 + 0];
            acc1 += qv * w_s[kk][jg * 2 + 1];
        }
        __syncthreads();
    }
    int j0 = jt * 8 + jg * 2;
    g_q[b * 2048 + j0 + 0] = acc0 + bq[j0 + 0];
    g_q[b * 2048 + j0 + 1] = acc1 + bq[j0 + 1];
}

// ---------------- K2: scores as smem-tiled GEMM + chunk softmax -----------
// grid (32 cc, 64 b), 256 thr. thread = (hp, l): hp = tid>>6, l = tid&63.
__global__ void __launch_bounds__(256) k_scores(const float* __restrict__ keys,
                                                const float* __restrict__ rpe,
                                                const int* __restrict__ steps) {
    int c = blockIdx.x, b = blockIdx.y;
    int lbase = c * SCH;
    int n = steps[b];
    if (lbase >= n) return;
    int nv = n - lbase; if (nv > SCH) nv = SCH;
    int tid = threadIdx.x;

    __shared__ float ks[64][71];                 // keys k-tile, pad 71 (bank-free)
    __shared__ unsigned long long q2[4 * 256];   // [hp][k] packed head-pair q
    __shared__ float r_s[SCH];
    __shared__ float s_s[8 * 68];

    // build q2 (coalesced): hp = it, k = tid
#pragma unroll
    for (int it = 0; it < 4; it++) {
        float lo = g_q[b * 2048 + (2 * it) * 256 + tid];
        float hi = g_q[b * 2048 + (2 * it + 1) * 256 + tid];
        unsigned long long p;
        PACK2(p, lo, hi);
        q2[it * 256 + tid] = p;
    }
    if (tid < SCH) r_s[tid] = rpe[(lbase + tid) * 64 + b];

    // tile prefetch state: 1024 float4 per tile, 4 per thread
    float4 buf[4];
    int rowv[4], colv[4];
#pragma unroll
    for (int it = 0; it < 4; it++) {
        int f4 = tid + it * 256;
        int row = f4 >> 4;
        rowv[it] = (row < nv) ? row : (nv - 1);  // clamp: harmless dup, masked later
        colv[it] = f4 & 15;
    }
#pragma unroll
    for (int it = 0; it < 4; it++)
        buf[it] = ((const float4*)keys)[((size_t)(lbase + rowv[it]) * 64 + b) * 64 + 0 * 16 + colv[it]];

    int hp = tid >> 6, l = tid & 63;
    unsigned long long acc = 0ull;

#pragma unroll
    for (int t = 0; t < 4; t++) {
        // store prefetched tile (scalar stores: rows pad-71 not 16B-aligned)
#pragma unroll
        for (int it = 0; it < 4; it++) {
            int f4 = tid + it * 256;
            int row = f4 >> 4, col = colv[it];
            ks[row][col * 4 + 0] = buf[it].x;
            ks[row][col * 4 + 1] = buf[it].y;
            ks[row][col * 4 + 2] = buf[it].z;
            ks[row][col * 4 + 3] = buf[it].w;
        }
        __syncthreads();
        if (t < 3) {
#pragma unroll
            for (int it = 0; it < 4; it++)
                buf[it] = ((const float4*)keys)[((size_t)(lbase + rowv[it]) * 64 + b) * 64 + (t + 1) * 16 + colv[it]];
        }
        // compute: acc += ks[l][kk] * q2[hp][t*64+kk]
        const unsigned long long* qp = q2 + hp * 256 + t * 64;
        const float* kr = ks[l];
#pragma unroll
        for (int kk = 0; kk < 64; kk++) {
            float kv = kr[kk];
            unsigned long long vv;
            PACK2(vv, kv, kv);
            FFMA2(acc, vv, qp[kk]);
        }
        __syncthreads();
    }

    // write scores to s_s (rpe-modulated)
    {
        float lo, hi;
        UNPACK2(lo, hi, acc);
        float r = r_s[l];
        s_s[(2 * hp) * 68 + l]     = lo * r;
        s_s[(2 * hp + 1) * 68 + l] = hi * r;
    }
    __syncthreads();

    // ---- phase B: chunk-local max + sum-exp; write exp weights [h][l] ----
    {
        int h = tid >> 5, lane = tid & 31;
        float m = -3.0e38f;
        for (int ll = lane; ll < nv; ll += 32) m = fmaxf(m, s_s[h * 68 + ll]);
#pragma unroll
        for (int o = 16; o > 0; o >>= 1) m = fmaxf(m, __shfl_xor_sync(0xffffffffu, m, o));
        float s = 0.f;
        size_t wbase = (size_t)(c * 64 + b) * 512 + h * 64;
        for (int ll = lane; ll < nv; ll += 32) {
            float p = __expf(s_s[h * 68 + ll] - m);
            g_wexp[wbase + ll] = p;
            s += p;
        }
#pragma unroll
        for (int o = 16; o > 0; o >>= 1) s += __shfl_xor_sync(0xffffffffu, s, o);
        if (lane == 0) {
            g_mc[(c * 64 + b) * 8 + h] = m;
            g_sc[(c * 64 + b) * 8 + h] = s;
        }
    }
}

// ---------------- K3: weighted read (f32x2), normalized on the fly --------
__global__ void __launch_bounds__(256) k_read(const float* __restrict__ vals,
                                              const int* __restrict__ steps) {
    int cb = blockIdx.x, b = blockIdx.y;
    int lbase = cb * RCH;
    int n = steps[b];
    if (lbase >= n) return;
    int nv = n - lbase; if (nv > RCH) nv = RCH;
    int tid = threadIdx.x;
    int nc_all = (n + SCH - 1) >> 6;

    __shared__ float f_s[8][32];
    __shared__ __align__(16) float w_s[RCH * 8];

    {
        int h = tid >> 5, cc = tid & 31;
        int valid = cc < nc_all;
        float m = valid ? g_mc[(cc * 64 + b) * 8 + h] : -3.0e38f;
        float s = valid ? g_sc[(cc * 64 + b) * 8 + h] : 0.f;
        float M = m;
#pragma unroll
        for (int o = 16; o > 0; o >>= 1) M = fmaxf(M, __shfl_xor_sync(0xffffffffu, M, o));
        float e = __expf(m - M);
        float denom = e * s;
#pragma unroll
        for (int o = 16; o > 0; o >>= 1) denom += __shfl_xor_sync(0xffffffffu, denom, o);
        f_s[h][cc] = e / denom;
    }
    __syncthreads();

    {
        int cc0 = cb * 2;
#pragma unroll
        for (int it = 0; it < 4; it++) {
            int i = tid + it * 256;          // i = h*128 + l
            int h = i >> 7, l = i & 127;
            int cc = cc0 + (l >> 6);
            float wv = g_wexp[(size_t)(cc * 64 + b) * 512 + h * 64 + (l & 63)];
            w_s[l * 8 + h] = wv * f_s[h][cc];
        }
    }
    __syncthreads();

    unsigned long long ah[4];
#pragma unroll
    for (int i = 0; i < 4; i++) ah[i] = 0ull;
    const float* vp = vals + ((size_t)lbase * 64 + b) * 256 + tid;
    const unsigned long long* wll = (const unsigned long long*)w_s;
    int l = 0;
    for (; l + 16 <= nv; l += 16) {
        float v[16];
#pragma unroll
        for (int i = 0; i < 16; i++) v[i] = vp[(size_t)(l + i) * 16384];
#pragma unroll
        for (int i = 0; i < 16; i++) {
            unsigned long long vv;
            PACK2(vv, v[i], v[i]);
#pragma unroll
            for (int hpp = 0; hpp < 4; hpp++)
                FFMA2(ah[hpp], wll[(l + i) * 4 + hpp], vv);
        }
    }
    for (; l < nv; l++) {
        float v = vp[(size_t)l * 16384];
        unsigned long long vv;
        PACK2(vv, v, v);
#pragma unroll
        for (int hpp = 0; hpp < 4; hpp++)
            FFMA2(ah[hpp], wll[l * 4 + hpp], vv);
    }
    size_t pbase = ((size_t)cb * 64 + b) * 2048;
#pragma unroll
    for (int hpp = 0; hpp < 4; hpp++) {
        float lo, hi;
        UNPACK2(lo, hi, ah[hpp]);
        g_rpart[pbase + (hpp * 2 + 0) * 256 + tid] = lo;
        g_rpart[pbase + (hpp * 2 + 1) * 256 + tid] = hi;
    }
}

// ---------------- K4: out partial GEMM with predicated chunk reduce -------
__global__ void __launch_bounds__(256) k_outgemm(const float* __restrict__ Wa,
                                                 const int* __restrict__ steps) {
    int kc = blockIdx.x, bt = blockIdx.y;
    int tid = threadIdx.x;
    __shared__ __align__(16) float R_s[128 * 8];   // [k][bi]
    __shared__ int nc_s[8];
    if (tid < 8) nc_s[tid] = (steps[bt * 8 + tid] + RCH - 1) >> 7;
    __syncthreads();

    for (int i = tid; i < 1024; i += 256) {
        int bi = i >> 7, k = i & 127;
        int b = bt * 8 + bi;
        int nc = nc_s[bi];
        float s = 0.f;
#pragma unroll
        for (int cc = 0; cc < 16; cc++)
            if (cc < nc) s += g_rpart[((size_t)cc * 64 + b) * 2048 + kc * 128 + k];
        R_s[k * 8 + bi] = s;
    }
    __syncthreads();

    float acc[8];
#pragma unroll
    for (int i = 0; i < 8; i++) acc[i] = 0.f;
    const float4* R4 = (const float4*)R_s;
#pragma unroll 4
    for (int k = 0; k < 128; k++) {
        float wa = Wa[(size_t)(kc * 128 + k) * 256 + tid];
        float4 r0 = R4[k * 2], r1 = R4[k * 2 + 1];
        acc[0] += r0.x * wa; acc[1] += r0.y * wa; acc[2] += r0.z * wa; acc[3] += r0.w * wa;
        acc[4] += r1.x * wa; acc[5] += r1.y * wa; acc[6] += r1.z * wa; acc[7] += r1.w * wa;
    }
#pragma unroll
    for (int bi = 0; bi < 8; bi++)
        g_opart[((size_t)kc * 64 + bt * 8 + bi) * 256 + tid] = acc[bi];
}

// ---------------- K5: final reduce + bias ---------------------------------
__global__ void __launch_bounds__(256) k_final(const float* __restrict__ ba,
                                               float* __restrict__ out) {
    int b = blockIdx.x, vo = threadIdx.x;
    float s = ba[vo];
#pragma unroll
    for (int cc = 0; cc < 16; cc++) s += g_opart[((size_t)cc * 64 + b) * 256 + vo];
    out[b * 256 + vo] = s;
}

// ---------------- launch --------------------------------------------------
extern "C" void kernel_launch(void* const* d_in, const int* in_sizes, int n_in,
                              void* d_out, int out_size) {
    const float* query = (const float*)d_in[0];
    const float* keys  = (const float*)d_in[1];
    const float* vals  = (const float*)d_in[2];
    const float* rpe   = (const float*)d_in[3];
    const float* Wq    = (const float*)d_in[4];
    const float* bq    = (const float*)d_in[5];
    const float* Wa    = (const float*)d_in[6];
    const float* ba    = (const float*)d_in[7];
    const int*   steps = (const int*)d_in[8];
    float* out = (float*)d_out;

    k_qgemm<<<256, 256>>>(query, Wq, bq);
    k_scores<<<dim3(NSC, BATCH), 256>>>(keys, rpe, steps);
    k_read<<<dim3(NRC, BATCH), 256>>>(vals, steps);
    k_outgemm<<<dim3(16, 8), 256>>>(Wa, steps);    // 4th -> profiled
    k_final<<<64, 256>>>(ba, out);
}

// round 8
// speedup vs baseline: 1.7527x; 1.0868x over previous
#include <cuda_runtime.h>
#include <math.h>
#include <string.h>

#define LEN   2048
#define BATCH 64
#define NH    8
#define SCH   64          // scores chunk
#define NSC   32          // # score chunks
#define RCH   128         // read chunk
#define NRC   16          // # read chunks

#define FFMA2(acc, x, y) \
    asm("fma.rn.f32x2 %0, %1, %2, %0;" : "+l"(acc) : "l"(x), "l"(y))
#define PACK2(out, lo, hi) \
    asm("mov.b64 %0, {%1, %2};" : "=l"(out) : "f"(lo), "f"(hi))
#define UNPACK2(lo, hi, in) \
    asm("mov.b64 {%0, %1}, %2;" : "=f"(lo), "=f"(hi) : "l"(in))

// ---------------- scratch (device globals; no allocation) ----------------
__device__ float g_q[BATCH * 2048];              // q[b][h*256+k]
__device__ float g_wexp[NSC * BATCH * SCH * NH]; // exp weights [cc][b][h*64+l]
__device__ float g_mc[NSC * BATCH * NH];         // chunk-local max
__device__ float g_sc[NSC * BATCH * NH];         // chunk-local sum-exp
__device__ float g_rpart[NRC * BATCH * 2048];    // normalized read partials
__device__ float g_read[BATCH * 2048];           // merged read [b][h*256+v]
__device__ float g_opart[32 * BATCH * 256];      // kc partials of out

// ---------------- K1: q GEMM: q = query@Wq + bq ---------------------------
__global__ void __launch_bounds__(256) k_qgemm(const float* __restrict__ query,
                                               const float* __restrict__ Wq,
                                               const float* __restrict__ bq) {
    __shared__ float w_s[32][10];    // [k][j] pad
    __shared__ float q_s[64][33];    // [b][k] pad
    int jt = blockIdx.x;
    int tid = threadIdx.x;
    int b = tid & 63, jg = tid >> 6;
    float acc0 = 0.f, acc1 = 0.f;
    for (int kt = 0; kt < 8; kt++) {
        {   // Wq tile 32k x 8j
            int k = tid >> 3, j = tid & 7;
            w_s[k][j] = Wq[(size_t)(kt * 32 + k) * 2048 + jt * 8 + j];
        }
#pragma unroll
        for (int it = 0; it < 2; it++) {   // query tile 64b x 32k, float4
            int f4 = tid + it * 256;
            int bb = f4 >> 3, k4 = f4 & 7;
            float4 v = ((const float4*)query)[bb * 64 + kt * 8 + k4];
            q_s[bb][k4 * 4 + 0] = v.x;
            q_s[bb][k4 * 4 + 1] = v.y;
            q_s[bb][k4 * 4 + 2] = v.z;
            q_s[bb][k4 * 4 + 3] = v.w;
        }
        __syncthreads();
#pragma unroll
        for (int kk = 0; kk < 32; kk++) {
            float qv = q_s[b][kk];
            acc0 += qv * w_s[kk][jg * 2 + 0];
            acc1 += qv * w_s[kk][jg * 2 + 1];
        }
        __syncthreads();
    }
    int j0 = jt * 8 + jg * 2;
    g_q[b * 2048 + j0 + 0] = acc0 + bq[j0 + 0];
    g_q[b * 2048 + j0 + 1] = acc1 + bq[j0 + 1];
}

// ---------------- K2: scores as smem-tiled GEMM + chunk softmax -----------
// grid (32 cc, 64 b), 256 thr. thread = (hp, l): hp = tid>>6, l = tid&63.
__global__ void __launch_bounds__(256) k_scores(const float* __restrict__ keys,
                                                const float* __restrict__ rpe,
                                                const int* __restrict__ steps) {
    int c = blockIdx.x, b = blockIdx.y;
    int lbase = c * SCH;
    int n = steps[b];
    if (lbase >= n) return;
    int nv = n - lbase; if (nv > SCH) nv = SCH;
    int tid = threadIdx.x;

    __shared__ float ks[64][71];                 // keys k-tile, pad 71
    __shared__ unsigned long long q2[4 * 256];   // [hp][k] packed head-pair q
    __shared__ float r_s[SCH];
    __shared__ float s_s[8 * 68];

#pragma unroll
    for (int it = 0; it < 4; it++) {
        float lo = g_q[b * 2048 + (2 * it) * 256 + tid];
        float hi = g_q[b * 2048 + (2 * it + 1) * 256 + tid];
        unsigned long long p;
        PACK2(p, lo, hi);
        q2[it * 256 + tid] = p;
    }
    if (tid < SCH) r_s[tid] = rpe[(lbase + tid) * 64 + b];

    float4 buf[4];
    int rowv[4], colv[4];
#pragma unroll
    for (int it = 0; it < 4; it++) {
        int f4 = tid + it * 256;
        int row = f4 >> 4;
        rowv[it] = (row < nv) ? row : (nv - 1);
        colv[it] = f4 & 15;
    }
#pragma unroll
    for (int it = 0; it < 4; it++)
        buf[it] = ((const float4*)keys)[((size_t)(lbase + rowv[it]) * 64 + b) * 64 + 0 * 16 + colv[it]];

    int hp = tid >> 6, l = tid & 63;
    unsigned long long acc = 0ull;

#pragma unroll
    for (int t = 0; t < 4; t++) {
#pragma unroll
        for (int it = 0; it < 4; it++) {
            int f4 = tid + it * 256;
            int row = f4 >> 4, col = colv[it];
            ks[row][col * 4 + 0] = buf[it].x;
            ks[row][col * 4 + 1] = buf[it].y;
            ks[row][col * 4 + 2] = buf[it].z;
            ks[row][col * 4 + 3] = buf[it].w;
        }
        __syncthreads();
        if (t < 3) {
#pragma unroll
            for (int it = 0; it < 4; it++)
                buf[it] = ((const float4*)keys)[((size_t)(lbase + rowv[it]) * 64 + b) * 64 + (t + 1) * 16 + colv[it]];
        }
        const unsigned long long* qp = q2 + hp * 256 + t * 64;
        const float* kr = ks[l];
#pragma unroll
        for (int kk = 0; kk < 64; kk++) {
            float kv = kr[kk];
            unsigned long long vv;
            PACK2(vv, kv, kv);
            FFMA2(acc, vv, qp[kk]);
        }
        __syncthreads();
    }

    {
        float lo, hi;
        UNPACK2(lo, hi, acc);
        float r = r_s[l];
        s_s[(2 * hp) * 68 + l]     = lo * r;
        s_s[(2 * hp + 1) * 68 + l] = hi * r;
    }
    __syncthreads();

    {
        int h = tid >> 5, lane = tid & 31;
        float m = -3.0e38f;
        for (int ll = lane; ll < nv; ll += 32) m = fmaxf(m, s_s[h * 68 + ll]);
#pragma unroll
        for (int o = 16; o > 0; o >>= 1) m = fmaxf(m, __shfl_xor_sync(0xffffffffu, m, o));
        float s = 0.f;
        size_t wbase = (size_t)(c * 64 + b) * 512 + h * 64;
        for (int ll = lane; ll < nv; ll += 32) {
            float p = __expf(s_s[h * 68 + ll] - m);
            g_wexp[wbase + ll] = p;
            s += p;
        }
#pragma unroll
        for (int o = 16; o > 0; o >>= 1) s += __shfl_xor_sync(0xffffffffu, s, o);
        if (lane == 0) {
            g_mc[(c * 64 + b) * 8 + h] = m;
            g_sc[(c * 64 + b) * 8 + h] = s;
        }
    }
}

// ---------------- K3: weighted read (f32x2), normalized on the fly --------
__global__ void __launch_bounds__(256) k_read(const float* __restrict__ vals,
                                              const int* __restrict__ steps) {
    int cb = blockIdx.x, b = blockIdx.y;
    int lbase = cb * RCH;
    int n = steps[b];
    if (lbase >= n) return;
    int nv = n - lbase; if (nv > RCH) nv = RCH;
    int tid = threadIdx.x;
    int nc_all = (n + SCH - 1) >> 6;

    __shared__ float f_s[8][32];
    __shared__ __align__(16) float w_s[RCH * 8];

    {
        int h = tid >> 5, cc = tid & 31;
        int valid = cc < nc_all;
        float m = valid ? g_mc[(cc * 64 + b) * 8 + h] : -3.0e38f;
        float s = valid ? g_sc[(cc * 64 + b) * 8 + h] : 0.f;
        float M = m;
#pragma unroll
        for (int o = 16; o > 0; o >>= 1) M = fmaxf(M, __shfl_xor_sync(0xffffffffu, M, o));
        float e = __expf(m - M);
        float denom = e * s;
#pragma unroll
        for (int o = 16; o > 0; o >>= 1) denom += __shfl_xor_sync(0xffffffffu, denom, o);
        f_s[h][cc] = e / denom;
    }
    __syncthreads();

    {
        int cc0 = cb * 2;
#pragma unroll
        for (int it = 0; it < 4; it++) {
            int i = tid + it * 256;          // i = h*128 + l
            int h = i >> 7, l = i & 127;
            int cc = cc0 + (l >> 6);
            float wv = g_wexp[(size_t)(cc * 64 + b) * 512 + h * 64 + (l & 63)];
            w_s[l * 8 + h] = wv * f_s[h][cc];
        }
    }
    __syncthreads();

    unsigned long long ah[4];
#pragma unroll
    for (int i = 0; i < 4; i++) ah[i] = 0ull;
    const float* vp = vals + ((size_t)lbase * 64 + b) * 256 + tid;
    const unsigned long long* wll = (const unsigned long long*)w_s;
    int l = 0;
    for (; l + 16 <= nv; l += 16) {
        float v[16];
#pragma unroll
        for (int i = 0; i < 16; i++) v[i] = vp[(size_t)(l + i) * 16384];
#pragma unroll
        for (int i = 0; i < 16; i++) {
            unsigned long long vv;
            PACK2(vv, v[i], v[i]);
#pragma unroll
            for (int hpp = 0; hpp < 4; hpp++)
                FFMA2(ah[hpp], wll[(l + i) * 4 + hpp], vv);
        }
    }
    for (; l < nv; l++) {
        float v = vp[(size_t)l * 16384];
        unsigned long long vv;
        PACK2(vv, v, v);
#pragma unroll
        for (int hpp = 0; hpp < 4; hpp++)
            FFMA2(ah[hpp], wll[l * 4 + hpp], vv);
    }
    size_t pbase = ((size_t)cb * 64 + b) * 2048;
#pragma unroll
    for (int hpp = 0; hpp < 4; hpp++) {
        float lo, hi;
        UNPACK2(lo, hi, ah[hpp]);
        g_rpart[pbase + (hpp * 2 + 0) * 256 + tid] = lo;
        g_rpart[pbase + (hpp * 2 + 1) * 256 + tid] = hi;
    }
}

// ---------------- K3b: merge read chunk partials -> g_read ----------------
// grid (8 ib, 64 b), 256 thr: 16 independent predicated loads per thread
__global__ void __launch_bounds__(256) k_rmerge(const int* __restrict__ steps) {
    int b = blockIdx.y;
    int i = blockIdx.x * 256 + threadIdx.x;      // 0..2047
    int nc = (steps[b] + RCH - 1) >> 7;
    float s = 0.f;
#pragma unroll
    for (int cc = 0; cc < 16; cc++)
        if (cc < nc) s += g_rpart[((size_t)cc * 64 + b) * 2048 + i];
    g_read[b * 2048 + i] = s;
}

// ---------------- K4: out partial GEMM, kc of 64 -> grid (32,8) -----------
__global__ void __launch_bounds__(256) k_outgemm(const float* __restrict__ Wa) {
    int kc = blockIdx.x, bt = blockIdx.y;
    int tid = threadIdx.x;
    __shared__ __align__(16) float R_s[64 * 8];  // [k][bi]
#pragma unroll
    for (int it = 0; it < 2; it++) {
        int i = tid + it * 256;
        int bi = i >> 6, k = i & 63;
        R_s[k * 8 + bi] = g_read[(bt * 8 + bi) * 2048 + kc * 64 + k];
    }
    __syncthreads();

    unsigned long long acc[4];
#pragma unroll
    for (int p = 0; p < 4; p++) acc[p] = 0ull;
    const unsigned long long* R2 = (const unsigned long long*)R_s;
#pragma unroll 8
    for (int k = 0; k < 64; k++) {
        float wa = Wa[(size_t)(kc * 64 + k) * 256 + tid];
        unsigned long long wv;
        PACK2(wv, wa, wa);
#pragma unroll
        for (int p = 0; p < 4; p++)
            FFMA2(acc[p], R2[k * 4 + p], wv);
    }
#pragma unroll
    for (int p = 0; p < 4; p++) {
        float lo, hi;
        UNPACK2(lo, hi, acc[p]);
        g_opart[((size_t)kc * 64 + bt * 8 + 2 * p + 0) * 256 + tid] = lo;
        g_opart[((size_t)kc * 64 + bt * 8 + 2 * p + 1) * 256 + tid] = hi;
    }
}

// ---------------- K5: final reduce + bias ---------------------------------
__global__ void __launch_bounds__(256) k_final(const float* __restrict__ ba,
                                               float* __restrict__ out) {
    int b = blockIdx.x, vo = threadIdx.x;
    float s = ba[vo];
#pragma unroll
    for (int cc = 0; cc < 32; cc++) s += g_opart[((size_t)cc * 64 + b) * 256 + vo];
    out[b * 256 + vo] = s;
}

// ---------------- launch --------------------------------------------------
extern "C" void kernel_launch(void* const* d_in, const int* in_sizes, int n_in,
                              void* d_out, int out_size) {
    const float* query = (const float*)d_in[0];
    const float* keys  = (const float*)d_in[1];
    const float* vals  = (const float*)d_in[2];
    const float* rpe   = (const float*)d_in[3];
    const float* Wq    = (const float*)d_in[4];
    const float* bq    = (const float*)d_in[5];
    const float* Wa    = (const float*)d_in[6];
    const float* ba    = (const float*)d_in[7];
    const int*   steps = (const int*)d_in[8];
    float* out = (float*)d_out;

    k_qgemm<<<256, 256>>>(query, Wq, bq);
    k_scores<<<dim3(NSC, BATCH), 256>>>(keys, rpe, steps);
    k_read<<<dim3(NRC, BATCH), 256>>>(vals, steps);
    k_rmerge<<<dim3(8, BATCH), 256>>>(steps);      // 4th -> profiled
    k_outgemm<<<dim3(32, 8), 256>>>(Wa);
    k_final<<<64, 256>>>(ba, out);
}